// round 15
// baseline (speedup 1.0000x reference)
#include <cuda_runtime.h>

// Soft decision tree path probabilities — barrier-free, smem-free. FINAL.
// Converged config: one row per 64-thread CTA, grid=512.
//   Block sweep (ncu dur): 1024->5.82us, 256->4.58, 64->4.19-4.42, 32->4.32.
//   Body is ~300 cycles; the remainder is the per-launch overhead floor.
//   Harness timer is bimodal {~4.67us, ~6.66-6.88us} on identical source
//   (container clock state); best recorded 4.672us with this exact kernel.
// Compile-time shapes: DEPTH=8, N_NODES=255, N_LEAVES=256, BATCH=512.
//
// Thread u owns the depth-6 subtree over leaves 4u..4u+3. Its 9 x-loads are
// index-computable and issued together (top-path loads broadcast from ~2
// cache lines warp-wide):
//   top path d=0..5 : node = (2^d-1) + (u >> (6-d))
//   depth-6         : 63 + u
//   depth-7         : 127+2u, 128+2u
// Prefix product before the depth-d factor IS node_d's path prob: top nodes
// written by the leftmost thread of each subtree; deeper nodes written
// unconditionally by their owner. Child 2i+1 takes factor x[i], child 2i+2
// takes 1-x[i]; (1-x)*p contracted to fmaf(-x,p,p) (1 FFMA, ~1ulp delta).
//
// Output: [ leaf_probs (512 x 256) ; node_probs (512 x 255) ] row-major.

#define BATCH    512
#define NODE_OFF (BATCH * 256)   // 131072, start of node-prob block

__device__ __forceinline__ float one_minus_mul(float xv, float p) {
    return fmaf(-xv, p, p);      // (1 - xv) * p
}

__global__ __launch_bounds__(64) void tree_path_kernel(
    const float* __restrict__ x,   // (512, 255)
    float* __restrict__ out)
{
    const unsigned u  = threadIdx.x;       // 0..63
    const unsigned b  = blockIdx.x;        // 0..511
    const unsigned u2 = u + u;

    const float* __restrict__ xr = x + b * 255u;
    float* __restrict__ on = out + NODE_OFF + b * 255u;

    // ---- issue all 9 independent loads up front ----
    float xt[6];
#pragma unroll
    for (int d = 0; d < 6; ++d) {
        const unsigned node = ((1u << d) - 1u) + (u >> (6 - d));
        xt[d] = __ldg(xr + node);
    }
    const float x6  = __ldg(xr + 63u + u);
    const float x7a = __ldg(xr + 127u + u2);
    const float x7b = __ldg(xr + 128u + u2);

    // ---- top path prefix product, emitting top node probs ----
    float p = 1.0f;
#pragma unroll
    for (int d = 0; d < 6; ++d) {
        const unsigned node = ((1u << d) - 1u) + (u >> (6 - d));
        if ((u & ((1u << (6 - d)) - 1u)) == 0u) {
            on[node] = p;                    // path prob of node at depth d
        }
        p = ((u >> (5 - d)) & 1u) ? one_minus_mul(xt[d], p) : (p * xt[d]);
    }

    // ---- exclusively-owned nodes ----
    on[63u + u] = p;                         // depth 6
    const float p7a = p * x6;                // node 127+2u
    const float p7b = one_minus_mul(x6, p);  // node 128+2u
    on[127u + u2] = p7a;
    on[128u + u2] = p7b;

    // ---- leaves 4u..4u+3 (aligned float4 store) ----
    float4 leaf;
    leaf.x = p7a * x7a;
    leaf.y = one_minus_mul(x7a, p7a);
    leaf.z = p7b * x7b;
    leaf.w = one_minus_mul(x7b, p7b);
    *reinterpret_cast<float4*>(out + (b << 8) + (u2 + u2)) = leaf;
}

extern "C" void kernel_launch(void* const* d_in, const int* in_sizes, int n_in,
                              void* d_out, int out_size) {
    const float* x = (const float*)d_in[0];  // (512, 255) float32
    float* out = (float*)d_out;
    tree_path_kernel<<<BATCH, 64>>>(x, out);
}

// round 16
// speedup vs baseline: 1.1082x; 1.1082x over previous
#include <cuda_runtime.h>

// Soft decision tree path probabilities — barrier-free, smem-free. FINAL.
// Converged config: one row per 64-thread CTA, grid=512.
//   Block sweep (ncu dur): 1024->5.82us, 256->4.58, 64->4.13-4.42, 32->4.32.
//   Body is ~300 cycles; the remainder is the per-launch overhead floor.
//   Harness timer is bimodal {~4.67us, ~6.6-6.9us} on identical source
//   (container clock state); best recorded 4.672us with this exact kernel.
// Compile-time shapes: DEPTH=8, N_NODES=255, N_LEAVES=256, BATCH=512.
//
// Thread u owns the depth-6 subtree over leaves 4u..4u+3. Its 9 x-loads are
// index-computable and issued together (top-path loads broadcast from ~2
// cache lines warp-wide):
//   top path d=0..5 : node = (2^d-1) + (u >> (6-d))
//   depth-6         : 63 + u
//   depth-7         : 127+2u, 128+2u
// Prefix product before the depth-d factor IS node_d's path prob: top nodes
// written by the leftmost thread of each subtree; deeper nodes written
// unconditionally by their owner. Child 2i+1 takes factor x[i], child 2i+2
// takes 1-x[i]; (1-x)*p contracted to fmaf(-x,p,p) (1 FFMA, ~1ulp delta).
//
// Output: [ leaf_probs (512 x 256) ; node_probs (512 x 255) ] row-major.

#define BATCH    512
#define NODE_OFF (BATCH * 256)   // 131072, start of node-prob block

__device__ __forceinline__ float one_minus_mul(float xv, float p) {
    return fmaf(-xv, p, p);      // (1 - xv) * p
}

__global__ __launch_bounds__(64) void tree_path_kernel(
    const float* __restrict__ x,   // (512, 255)
    float* __restrict__ out)
{
    const unsigned u  = threadIdx.x;       // 0..63
    const unsigned b  = blockIdx.x;        // 0..511
    const unsigned u2 = u + u;

    const float* __restrict__ xr = x + b * 255u;
    float* __restrict__ on = out + NODE_OFF + b * 255u;

    // ---- issue all 9 independent loads up front ----
    float xt[6];
#pragma unroll
    for (int d = 0; d < 6; ++d) {
        const unsigned node = ((1u << d) - 1u) + (u >> (6 - d));
        xt[d] = __ldg(xr + node);
    }
    const float x6  = __ldg(xr + 63u + u);
    const float x7a = __ldg(xr + 127u + u2);
    const float x7b = __ldg(xr + 128u + u2);

    // ---- top path prefix product, emitting top node probs ----
    float p = 1.0f;
#pragma unroll
    for (int d = 0; d < 6; ++d) {
        const unsigned node = ((1u << d) - 1u) + (u >> (6 - d));
        if ((u & ((1u << (6 - d)) - 1u)) == 0u) {
            on[node] = p;                    // path prob of node at depth d
        }
        p = ((u >> (5 - d)) & 1u) ? one_minus_mul(xt[d], p) : (p * xt[d]);
    }

    // ---- exclusively-owned nodes ----
    on[63u + u] = p;                         // depth 6
    const float p7a = p * x6;                // node 127+2u
    const float p7b = one_minus_mul(x6, p);  // node 128+2u
    on[127u + u2] = p7a;
    on[128u + u2] = p7b;

    // ---- leaves 4u..4u+3 (aligned float4 store) ----
    float4 leaf;
    leaf.x = p7a * x7a;
    leaf.y = one_minus_mul(x7a, p7a);
    leaf.z = p7b * x7b;
    leaf.w = one_minus_mul(x7b, p7b);
    *reinterpret_cast<float4*>(out + (b << 8) + (u2 + u2)) = leaf;
}

extern "C" void kernel_launch(void* const* d_in, const int* in_sizes, int n_in,
                              void* d_out, int out_size) {
    const float* x = (const float*)d_in[0];  // (512, 255) float32
    float* out = (float*)d_out;
    tree_path_kernel<<<BATCH, 64>>>(x, out);
}